// round 1
// baseline (speedup 1.0000x reference)
#include <cuda_runtime.h>
#include <math.h>
#include <stdint.h>

// ---------------- problem constants ----------------
#define BB   2
#define TT   2048
#define DD   1024
#define HH   16
#define DH   64
#define LL   6
#define VV   50257
#define FF   4096
#define MM_  (BB*TT)          // 4096 rows
#define KMIN (TT - 512)       // 1536 : allowed j <= max(i, KMIN)

// ---------------- scratch (device globals; no allocation) ----------------
__device__ float g_x [MM_*DD];
__device__ float g_h [MM_*DD];
__device__ float g_q [MM_*DD];
__device__ float g_k [MM_*DD];
__device__ float g_v [MM_*DD];
__device__ float g_y [MM_*DD];
__device__ float g_m1[(size_t)MM_*FF];

// ---------------- embedding gather ----------------
__global__ void embed_k(const int* __restrict__ idx,
                        const float* __restrict__ emb,
                        float* __restrict__ x) {
    int row = blockIdx.x;                 // 0..MM_-1
    int tok = idx[row];
    const float4* src = (const float4*)&emb[(size_t)tok * DD];
    float4* dst = (float4*)&x[(size_t)row * DD];
    for (int i = threadIdx.x; i < DD/4; i += blockDim.x) dst[i] = src[i];
}

// ---------------- layernorm (row per block) ----------------
__global__ void ln_k(const float* __restrict__ x,
                     const float* __restrict__ w,
                     const float* __restrict__ b,
                     float* __restrict__ o) {
    int row = blockIdx.x;
    const float* xr = x + (size_t)row * DD;
    float s = 0.f, s2 = 0.f;
    for (int i = threadIdx.x; i < DD; i += 256) {
        float v = xr[i]; s += v; s2 += v * v;
    }
    // block reduction
    __shared__ float rs[8], rs2[8];
    for (int off = 16; off > 0; off >>= 1) {
        s  += __shfl_down_sync(0xffffffffu, s,  off);
        s2 += __shfl_down_sync(0xffffffffu, s2, off);
    }
    int wid = threadIdx.x >> 5, lid = threadIdx.x & 31;
    if (lid == 0) { rs[wid] = s; rs2[wid] = s2; }
    __syncthreads();
    if (wid == 0) {
        s  = (lid < 8) ? rs[lid]  : 0.f;
        s2 = (lid < 8) ? rs2[lid] : 0.f;
        for (int off = 4; off > 0; off >>= 1) {
            s  += __shfl_down_sync(0xffffffffu, s,  off);
            s2 += __shfl_down_sync(0xffffffffu, s2, off);
        }
        if (lid == 0) { rs[0] = s; rs2[0] = s2; }
    }
    __syncthreads();
    float mean = rs[0] * (1.0f / DD);
    float var  = rs2[0] * (1.0f / DD) - mean * mean;
    float inv  = rsqrtf(var + 1e-5f);
    float* orow = o + (size_t)row * DD;
    for (int i = threadIdx.x; i < DD; i += 256)
        orow[i] = (xr[i] - mean) * inv * w[i] + b[i];
}

// ---------------- generic SGEMM: C = act(A@W + bias + res) ----------------
// A: [M,K] row-major, W: [K,N] row-major, C: [M,N]
// BM=BN=128, BK=8, 256 threads, 8x8 per thread.
#define GBM 128
#define GBN 128
#define GBK 8
template<int ACT>  // 0 = none, 1 = exact GELU
__global__ void __launch_bounds__(256)
gemm_k(const float* __restrict__ A, const float* __restrict__ W,
       const float* __restrict__ bias, const float* __restrict__ res,
       float* __restrict__ C, int M, int N, int K) {
    __shared__ float As[GBK][GBM];
    __shared__ float Bs[GBK][GBN];
    int tid = threadIdx.x;
    int cb = blockIdx.x * GBN;
    int rb = blockIdx.y * GBM;

    int arow = tid >> 1, ak = (tid & 1) * 4;       // A tile load: one float4/thread
    int brow = tid >> 5, bcol = (tid & 31) * 4;    // B tile load: 4 scalars/thread
    int tx = tid & 15, ty = tid >> 4;

    float acc[8][8];
#pragma unroll
    for (int i = 0; i < 8; i++)
#pragma unroll
        for (int j = 0; j < 8; j++) acc[i][j] = 0.f;

    for (int k0 = 0; k0 < K; k0 += GBK) {
        // A: M,K are multiples of tile sizes and K%4==0 -> aligned float4
        float4 a4 = *(const float4*)&A[(size_t)(rb + arow) * K + k0 + ak];
        As[ak+0][arow] = a4.x; As[ak+1][arow] = a4.y;
        As[ak+2][arow] = a4.z; As[ak+3][arow] = a4.w;
        // B: guarded scalar loads (N may not be multiple of 4; rows may be unaligned)
        {
            int gc = cb + bcol;
            const float* wp = &W[(size_t)(k0 + brow) * N + gc];
#pragma unroll
            for (int u = 0; u < 4; u++)
                Bs[brow][bcol + u] = (gc + u < N) ? wp[u] : 0.f;
        }
        __syncthreads();
#pragma unroll
        for (int kk = 0; kk < GBK; kk++) {
            float ar[8], br[8];
            *(float4*)&ar[0] = *(float4*)&As[kk][ty * 8];
            *(float4*)&ar[4] = *(float4*)&As[kk][ty * 8 + 4];
            *(float4*)&br[0] = *(float4*)&Bs[kk][tx * 8];
            *(float4*)&br[4] = *(float4*)&Bs[kk][tx * 8 + 4];
#pragma unroll
            for (int i = 0; i < 8; i++)
#pragma unroll
                for (int j = 0; j < 8; j++)
                    acc[i][j] = fmaf(ar[i], br[j], acc[i][j]);
        }
        __syncthreads();
    }
    // epilogue
#pragma unroll
    for (int i = 0; i < 8; i++) {
        int r = rb + ty * 8 + i;
#pragma unroll
        for (int j = 0; j < 8; j++) {
            int c = cb + tx * 8 + j;
            if (c < N) {
                float val = acc[i][j];
                if (bias) val += bias[c];
                if (res)  val += res[(size_t)r * N + c];
                if (ACT == 1) val = 0.5f * val * (1.0f + erff(val * 0.70710678118654752f));
                C[(size_t)r * N + c] = val;
            }
        }
    }
}

// ---------------- flash attention (fp32, online softmax) ----------------
// mask: allowed j <= max(i, KMIN)  (contiguous key range per row)
#define AQ 64          // query rows per block
#define AK 32          // key rows per tile
__global__ void __launch_bounds__(256)
attn_k(const float* __restrict__ q, const float* __restrict__ k,
       const float* __restrict__ v, float* __restrict__ y) {
    int bh = blockIdx.y;
    int b = bh / HH, h = bh % HH;
    int qs = blockIdx.x * AQ;

    __shared__ float Qs[AQ][DH + 1];
    __shared__ float Ks[AK][DH + 1];
    __shared__ float Vs[AK][DH + 1];
    __shared__ float Sm[AQ][AK + 1];
    __shared__ float rm[AQ], rl[AQ], ra[AQ];

    int tid = threadIdx.x;
    int tx = tid & 15, ty = tid >> 4;   // 16x16: 4 rows x (2 score-cols / 4 out-dims)

    // load Q tile (scalar, coalesced)
    for (int i = tid; i < AQ * DH; i += 256) {
        int r = i >> 6, c = i & 63;
        Qs[r][c] = q[(size_t)(b * TT + qs + r) * DD + h * DH + c];
    }
    if (tid < AQ) { rm[tid] = -1e30f; rl[tid] = 0.f; }
    __syncthreads();

    float O[4][4];
#pragma unroll
    for (int i = 0; i < 4; i++)
#pragma unroll
        for (int j = 0; j < 4; j++) O[i][j] = 0.f;

    int kmaxb = max(qs + AQ - 1, KMIN);
    int ntiles = (kmaxb + AK) / AK;     // ceil((kmax+1)/AK)
    const float scale = 0.125f;         // 1/sqrt(64)

    for (int kt = 0; kt < ntiles; kt++) {
        int ks0 = kt * AK;
        for (int i = tid; i < AK * DH; i += 256) {
            int r = i >> 6, c = i & 63;
            size_t gidx = (size_t)(b * TT + ks0 + r) * DD + h * DH + c;
            Ks[r][c] = k[gidx];
            Vs[r][c] = v[gidx];
        }
        __syncthreads();
        // scores: each thread 4 rows x 2 cols
#pragma unroll
        for (int rr = 0; rr < 4; rr++) {
            int r = ty * 4 + rr;
            int jmax = max(qs + r, KMIN);
#pragma unroll
            for (int cc = 0; cc < 2; cc++) {
                int c = tx * 2 + cc;
                float s = 0.f;
#pragma unroll
                for (int d = 0; d < DH; d++) s = fmaf(Qs[r][d], Ks[c][d], s);
                s *= scale;
                if (ks0 + c > jmax) s = -1e30f;
                Sm[r][c] = s;
            }
        }
        __syncthreads();
        // per-row online softmax update (one thread per row)
        if (tid < AQ) {
            float mo = rm[tid], mx = mo;
#pragma unroll
            for (int c = 0; c < AK; c++) mx = fmaxf(mx, Sm[tid][c]);
            float al = __expf(mo - mx);
            float sum = 0.f;
#pragma unroll
            for (int c = 0; c < AK; c++) {
                float p = __expf(Sm[tid][c] - mx);
                Sm[tid][c] = p; sum += p;
            }
            rm[tid] = mx; rl[tid] = rl[tid] * al + sum; ra[tid] = al;
        }
        __syncthreads();
        // O = O*alpha + P @ V
#pragma unroll
        for (int rr = 0; rr < 4; rr++) {
            int r = ty * 4 + rr;
            float al = ra[r];
#pragma unroll
            for (int dd = 0; dd < 4; dd++) {
                int d = tx * 4 + dd;
                float a = O[rr][dd] * al;
#pragma unroll
                for (int c = 0; c < AK; c++) a = fmaf(Sm[r][c], Vs[c][d], a);
                O[rr][dd] = a;
            }
        }
        __syncthreads();
    }
    // write out
#pragma unroll
    for (int rr = 0; rr < 4; rr++) {
        int r = ty * 4 + rr;
        float inv = 1.f / rl[r];
#pragma unroll
        for (int dd = 0; dd < 4; dd++) {
            y[(size_t)(b * TT + qs + r) * DD + h * DH + tx * 4 + dd] = O[rr][dd] * inv;
        }
    }
}

// ---------------- host orchestration ----------------
extern "C" void kernel_launch(void* const* d_in, const int* in_sizes, int n_in,
                              void* d_out, int out_size) {
    const int*   idx     = (const int*)  d_in[0];
    const float* tok_emb = (const float*)d_in[1];
    const float* ln1_w   = (const float*)d_in[2];
    const float* ln1_b   = (const float*)d_in[3];
    const float* Wq      = (const float*)d_in[4];
    const float* bq      = (const float*)d_in[5];
    const float* Wk      = (const float*)d_in[6];
    const float* bk      = (const float*)d_in[7];
    const float* Wv      = (const float*)d_in[8];
    const float* bv      = (const float*)d_in[9];
    const float* Wp      = (const float*)d_in[10];
    const float* bp      = (const float*)d_in[11];
    const float* ln2_w   = (const float*)d_in[12];
    const float* ln2_b   = (const float*)d_in[13];
    const float* W1      = (const float*)d_in[14];
    const float* b1      = (const float*)d_in[15];
    const float* W2      = (const float*)d_in[16];
    const float* b2      = (const float*)d_in[17];
    const float* lnf_w   = (const float*)d_in[18];
    const float* lnf_b   = (const float*)d_in[19];
    const float* head_w  = (const float*)d_in[20];
    float* out = (float*)d_out;

    float *x, *h, *q, *k, *v, *y, *m1;
    cudaGetSymbolAddress((void**)&x,  g_x);
    cudaGetSymbolAddress((void**)&h,  g_h);
    cudaGetSymbolAddress((void**)&q,  g_q);
    cudaGetSymbolAddress((void**)&k,  g_k);
    cudaGetSymbolAddress((void**)&v,  g_v);
    cudaGetSymbolAddress((void**)&y,  g_y);
    cudaGetSymbolAddress((void**)&m1, g_m1);

    embed_k<<<MM_, 256>>>(idx, tok_emb, x);

    dim3 gD (DD / GBN, MM_ / GBM);                       // N=1024
    dim3 gFF(FF / GBN, MM_ / GBM);                       // N=4096
    dim3 gV ((VV + GBN - 1) / GBN, MM_ / GBM);           // N=50257
    dim3 gAtt(TT / AQ, BB * HH);

    for (int l = 0; l < LL; l++) {
        const size_t oD  = (size_t)l * DD;
        const size_t oDD = (size_t)l * DD * DD;
        const size_t oFF = (size_t)l * FF;
        const size_t oDF = (size_t)l * DD * FF;

        ln_k<<<MM_, 256>>>(x, ln1_w + oD, ln1_b + oD, h);
        gemm_k<0><<<gD, 256>>>(h, Wq + oDD, bq + oD, nullptr, q, MM_, DD, DD);
        gemm_k<0><<<gD, 256>>>(h, Wk + oDD, bk + oD, nullptr, k, MM_, DD, DD);
        gemm_k<0><<<gD, 256>>>(h, Wv + oDD, bv + oD, nullptr, v, MM_, DD, DD);
        attn_k<<<gAtt, 256>>>(q, k, v, y);
        gemm_k<0><<<gD, 256>>>(y, Wp + oDD, bp + oD, x, x, MM_, DD, DD);

        ln_k<<<MM_, 256>>>(x, ln2_w + oD, ln2_b + oD, h);
        gemm_k<1><<<gFF, 256>>>(h, W1 + oDF, b1 + oFF, nullptr, m1, MM_, FF, DD);
        gemm_k<0><<<gD, 256>>>(m1, W2 + oDF, b2 + oD, x, x, MM_, DD, FF);
    }

    ln_k<<<MM_, 256>>>(x, lnf_w, lnf_b, h);
    gemm_k<0><<<gV, 256>>>(h, head_w, nullptr, nullptr, out, MM_, VV, DD);
}

// round 4
// speedup vs baseline: 1.8291x; 1.8291x over previous
#include <cuda_runtime.h>
#include <cuda_bf16.h>
#include <math.h>
#include <stdint.h>

// ---------------- problem constants ----------------
#define BB   2
#define TT   2048
#define DD   1024
#define HH   16
#define DH   64
#define LL   6
#define VV   50257
#define FF   4096
#define MM_  (BB*TT)          // 4096 rows
#define KMIN (TT - 512)       // 1536 : allowed j <= max(i, KMIN)
#define VPAD 50432            // VV padded to multiple of 256
#define QKVN 3072

// tcgen05 only exists on the arch-specific ('a') target. Guard so the plain
// compute_103 PTX pass compiles a SIMT fallback instead of dying in ptxas.
#if !defined(__CUDA_ARCH__) || defined(__CUDA_ARCH_FEAT_SM103_ALL) || defined(__CUDA_ARCH_FEAT_SM100_ALL) || defined(__CUDA_ARCH_FEAT_SM101_ALL)
#define HAS_TC 1
#else
#define HAS_TC 0
#endif

// ---------------- scratch (device globals; no allocation) ----------------
__device__ float          g_x   [MM_*DD];                 // residual stream fp32
__device__ __nv_bfloat16  g_hh  [MM_*DD];                 // LN output hi
__device__ __nv_bfloat16  g_hl  [MM_*DD];                 // LN output lo
__device__ float          g_qkv [(size_t)MM_*QKVN];       // fused qkv fp32
__device__ __nv_bfloat16  g_yh  [MM_*DD];                 // attn out hi
__device__ __nv_bfloat16  g_yl  [MM_*DD];                 // attn out lo
__device__ __nv_bfloat16  g_m1h [(size_t)MM_*FF];         // gelu out hi
__device__ __nv_bfloat16  g_m1l [(size_t)MM_*FF];         // gelu out lo
// transposed bf16 hi/lo weights  [N, K] K-major
__device__ __nv_bfloat16  g_wqkvh[(size_t)LL*QKVN*DD];
__device__ __nv_bfloat16  g_wqkvl[(size_t)LL*QKVN*DD];
__device__ __nv_bfloat16  g_wph  [(size_t)LL*DD*DD];
__device__ __nv_bfloat16  g_wpl  [(size_t)LL*DD*DD];
__device__ __nv_bfloat16  g_w1h  [(size_t)LL*FF*DD];
__device__ __nv_bfloat16  g_w1l  [(size_t)LL*FF*DD];
__device__ __nv_bfloat16  g_w2h  [(size_t)LL*DD*FF];
__device__ __nv_bfloat16  g_w2l  [(size_t)LL*DD*FF];
__device__ __nv_bfloat16  g_whh  [(size_t)VPAD*DD];
__device__ __nv_bfloat16  g_whl  [(size_t)VPAD*DD];
__device__ float          g_bqkv [LL*QKVN];

// ---------------- ptx helpers ----------------
static __device__ __forceinline__ uint32_t smem_u32(const void* p){
    uint32_t a;
    asm("{ .reg .u64 t; cvta.to.shared.u64 t, %1; cvt.u32.u64 %0, t; }":"=r"(a):"l"(p));
    return a;
}
static __device__ __forceinline__ void split_bf16(float v, __nv_bfloat16& hi, __nv_bfloat16& lo){
    hi = __float2bfloat16(v);
    lo = __float2bfloat16(v - __bfloat162float(hi));
}
#if HAS_TC
static __device__ __forceinline__ uint32_t elect_one(){
    uint32_t r;
    asm volatile("{ .reg .pred p; elect.sync _|p, 0xFFFFFFFF; selp.b32 %0,1,0,p; }":"=r"(r));
    return r;
}
static __device__ __forceinline__ void mbar_init(uint32_t a, uint32_t cnt){
    asm volatile("mbarrier.init.shared.b64 [%0], %1;" :: "r"(a), "r"(cnt) : "memory");
}
static __device__ __forceinline__ void mbar_wait(uint32_t a, uint32_t phase){
    asm volatile(
        "{\n\t.reg .pred P;\n"
        "WL_%=:\n\t"
        "mbarrier.try_wait.parity.acquire.cta.shared::cta.b64 P, [%0], %1;\n\t"
        "@!P bra WL_%=;\n\t"
        "}" :: "r"(a), "r"(phase) : "memory");
}
static __device__ __forceinline__ uint64_t mk_desc(uint32_t addr){
    // SW128, version=1 (Blackwell), SBO=64 (1024B per 8-row group), LBO=1
    return (uint64_t(2)<<61) | (uint64_t(1)<<46) | (uint64_t(64)<<32) | (uint64_t(1)<<16)
         | ((uint64_t)(addr>>4) & 0x3FFF);
}
static __device__ __forceinline__ void mma_f16_ss(uint32_t d, uint64_t ad, uint64_t bd,
                                                  uint32_t idesc, uint32_t en){
    asm volatile(
        "{\n\t.reg .pred p;\n\t"
        "setp.ne.u32 p, %4, 0;\n\t"
        "tcgen05.mma.cta_group::1.kind::f16 [%0], %1, %2, %3, {%5,%5,%5,%5}, p;\n\t"
        "}"
        :: "r"(d), "l"(ad), "l"(bd), "r"(idesc), "r"(en), "r"(0u) : "memory");
}
#define TC_LD32(r, ta) \
    asm volatile( \
        "tcgen05.ld.sync.aligned.32x32b.x32.b32 " \
        "{%0, %1, %2, %3, %4, %5, %6, %7, " \
        " %8, %9, %10, %11, %12, %13, %14, %15, " \
        " %16, %17, %18, %19, %20, %21, %22, %23, " \
        " %24, %25, %26, %27, %28, %29, %30, %31}, [%32];" \
        : "=r"((r)[0]),  "=r"((r)[1]),  "=r"((r)[2]),  "=r"((r)[3]), \
          "=r"((r)[4]),  "=r"((r)[5]),  "=r"((r)[6]),  "=r"((r)[7]), \
          "=r"((r)[8]),  "=r"((r)[9]),  "=r"((r)[10]), "=r"((r)[11]), \
          "=r"((r)[12]), "=r"((r)[13]), "=r"((r)[14]), "=r"((r)[15]), \
          "=r"((r)[16]), "=r"((r)[17]), "=r"((r)[18]), "=r"((r)[19]), \
          "=r"((r)[20]), "=r"((r)[21]), "=r"((r)[22]), "=r"((r)[23]), \
          "=r"((r)[24]), "=r"((r)[25]), "=r"((r)[26]), "=r"((r)[27]), \
          "=r"((r)[28]), "=r"((r)[29]), "=r"((r)[30]), "=r"((r)[31]) \
        : "r"(ta))
#endif // HAS_TC

// ---------------- embedding gather ----------------
__global__ void embed_k(const int* __restrict__ idx,
                        const float* __restrict__ emb,
                        float* __restrict__ x) {
    int row = blockIdx.x;
    int tok = idx[row];
    const float4* src = (const float4*)&emb[(size_t)tok * DD];
    float4* dst = (float4*)&x[(size_t)row * DD];
    for (int i = threadIdx.x; i < DD/4; i += blockDim.x) dst[i] = src[i];
}

// ---------------- layernorm: fp32 in -> bf16 hi/lo out ----------------
__global__ void ln_k(const float* __restrict__ x,
                     const float* __restrict__ w,
                     const float* __restrict__ b,
                     __nv_bfloat16* __restrict__ oh,
                     __nv_bfloat16* __restrict__ ol) {
    int row = blockIdx.x;
    const float* xr = x + (size_t)row * DD;
    float s = 0.f, s2 = 0.f;
    for (int i = threadIdx.x; i < DD; i += 256) {
        float v = xr[i]; s += v; s2 += v * v;
    }
    __shared__ float rs[8], rs2[8];
    for (int off = 16; off > 0; off >>= 1) {
        s  += __shfl_down_sync(0xffffffffu, s,  off);
        s2 += __shfl_down_sync(0xffffffffu, s2, off);
    }
    int wid = threadIdx.x >> 5, lid = threadIdx.x & 31;
    if (lid == 0) { rs[wid] = s; rs2[wid] = s2; }
    __syncthreads();
    if (wid == 0) {
        s  = (lid < 8) ? rs[lid]  : 0.f;
        s2 = (lid < 8) ? rs2[lid] : 0.f;
        for (int off = 4; off > 0; off >>= 1) {
            s  += __shfl_down_sync(0xffffffffu, s,  off);
            s2 += __shfl_down_sync(0xffffffffu, s2, off);
        }
        if (lid == 0) { rs[0] = s; rs2[0] = s2; }
    }
    __syncthreads();
    float mean = rs[0] * (1.0f / DD);
    float var  = rs2[0] * (1.0f / DD) - mean * mean;
    float inv  = rsqrtf(var + 1e-5f);
    for (int i = threadIdx.x; i < DD; i += 256) {
        float v = (xr[i] - mean) * inv * w[i] + b[i];
        __nv_bfloat16 hi, lo; split_bf16(v, hi, lo);
        oh[(size_t)row * DD + i] = hi;
        ol[(size_t)row * DD + i] = lo;
    }
}

// ---------------- weight convert+transpose: W[K,N] f32 -> hi/lo [N,K] bf16 ----------------
__global__ void convT_k(const float* __restrict__ W,
                        __nv_bfloat16* __restrict__ Wh,
                        __nv_bfloat16* __restrict__ Wl,
                        int K, int N) {
    __shared__ float t[32][33];
    int n0 = blockIdx.x * 32, k0 = blockIdx.y * 32;
    int tx = threadIdx.x, ty = threadIdx.y;   // 32 x 8
#pragma unroll
    for (int i = 0; i < 4; i++) {
        int k = k0 + ty + i*8;
        int n = n0 + tx;
        t[ty + i*8][tx] = (n < N) ? W[(size_t)k * N + n] : 0.f;
    }
    __syncthreads();
#pragma unroll
    for (int i = 0; i < 4; i++) {
        int n = n0 + ty + i*8;
        int k = k0 + tx;
        __nv_bfloat16 hi, lo; split_bf16(t[tx][ty + i*8], hi, lo);
        Wh[(size_t)n * K + k] = hi;
        Wl[(size_t)n * K + k] = lo;
    }
}

__global__ void cat_bias_k(const float* __restrict__ bq, const float* __restrict__ bk,
                           const float* __restrict__ bv, float* __restrict__ o) {
    int l = blockIdx.x, t = threadIdx.x;  // 1024 threads
    o[l*QKVN + t]          = bq[l*DD + t];
    o[l*QKVN + 1024 + t]   = bk[l*DD + t];
    o[l*QKVN + 2048 + t]   = bv[l*DD + t];
}

// ---------------- bf16x3 GEMM: C = act(A @ Bt^T + bias + res) ----------------
// A,Bt given as hi/lo bf16 K-major. D = Ah*Bh + Ah*Bl + Al*Bh (fp32 TMEM accum).
// Tile: 128(M) x 256(N), k-tiles of 64. grid=(N/256, M/128), 256 threads.
#define MT 128
#define NT 256
#define KT 64
#define TG_IDESC (0x490u | (16u<<17) | (8u<<24))   // f32 acc, bf16 a/b, N=128, M=128
#define STAGEB 98304                               // 16K+16K+32K+32K
#define SMEMB (1024 + 2*STAGEB)

template<int ACT, int OUTBF, int RES>
__global__ void __launch_bounds__(256)
tgemm_k(const __nv_bfloat16* __restrict__ Ah, const __nv_bfloat16* __restrict__ Al,
        const __nv_bfloat16* __restrict__ Bh, const __nv_bfloat16* __restrict__ Bl,
        const float* __restrict__ bias, const float* __restrict__ res,
        void* __restrict__ Cv, __nv_bfloat16* __restrict__ Clo,
        int M, int N, int K)
{
#if HAS_TC
    // ================= tcgen05 path (sm_103a cubin) =================
    extern __shared__ __align__(1024) char smc[];
    uint32_t sb = smem_u32(smc);
    const int tid = threadIdx.x, wid = tid >> 5, lid = tid & 31;
    const int rb = blockIdx.y * MT, cb = blockIdx.x * NT;

    if (wid == 0) {
        asm volatile("tcgen05.alloc.cta_group::1.sync.aligned.shared::cta.b32 [%0], %1;"
                     :: "r"(sb), "r"(256u) : "memory");
        asm volatile("tcgen05.relinquish_alloc_permit.cta_group::1.sync.aligned;");
    }
    if (tid == 0) { mbar_init(sb + 8, 1); mbar_init(sb + 16, 1); }
    __syncthreads();
    uint32_t tmem;
    asm volatile("ld.shared.b32 %0, [%1];" : "=r"(tmem) : "r"(sb));

    const int nk = K / KT;
    uint32_t ph0 = 0, ph1 = 0;

    for (int kt = 0; kt < nk; kt++) {
        const int s = kt & 1;
        char* stg = smc + 1024 + s * STAGEB;
        if (kt >= 2) {
            if (s == 0) { mbar_wait(sb + 8,  ph0); ph0 ^= 1; }
            else        { mbar_wait(sb + 16, ph1); ph1 ^= 1; }
        }
        // A tiles: 128 rows x 64 bf16 (128B rows, SW128 swizzled), hi then lo
        {
            const __nv_bfloat16* Abh = Ah + (size_t)rb * K + (size_t)kt * KT;
            const __nv_bfloat16* Abl = Al + (size_t)rb * K + (size_t)kt * KT;
#pragma unroll
            for (int j = 0; j < 4; j++) {
                int i = tid + j * 256;
                int r = i >> 3, u = i & 7;
                size_t go = (size_t)r * K + u * 8;
                int off = r * 128 + u * 16;
                int sw  = off ^ ((off >> 3) & 0x70);
                *(uint4*)(stg + sw)         = *(const uint4*)(Abh + go);
                *(uint4*)(stg + 16384 + sw) = *(const uint4*)(Abl + go);
            }
        }
        // B tiles: 256 rows x 64 bf16, hi then lo
        {
            const __nv_bfloat16* Bbh = Bh + (size_t)cb * K + (size_t)kt * KT;
            const __nv_bfloat16* Bbl = Bl + (size_t)cb * K + (size_t)kt * KT;
#pragma unroll
            for (int j = 0; j < 8; j++) {
                int i = tid + j * 256;
                int r = i >> 3, u = i & 7;
                size_t go = (size_t)r * K + u * 8;
                int off = r * 128 + u * 16;
                int sw  = off ^ ((off >> 3) & 0x70);
                *(uint4*)(stg + 32768 + sw) = *(const uint4*)(Bbh + go);
                *(uint4*)(stg + 65536 + sw) = *(const uint4*)(Bbl + go);
            }
        }
        asm volatile("fence.proxy.async.shared::cta;" ::: "memory");
        __syncthreads();
        if (wid == 0 && elect_one()) {
            uint32_t base = sb + 1024 + s * STAGEB;
            uint64_t adh  = mk_desc(base);
            uint64_t adl  = mk_desc(base + 16384);
            uint64_t bdh0 = mk_desc(base + 32768);
            uint64_t bdl0 = mk_desc(base + 65536);
            uint64_t bdh1 = bdh0 + 1024;   // +128 rows * 128B
            uint64_t bdl1 = bdl0 + 1024;
#pragma unroll
            for (int ks = 0; ks < 4; ks++) {
                uint32_t en = (kt > 0 || ks > 0) ? 1u : 0u;
                uint64_t o = ks * 2;
                mma_f16_ss(tmem,       adh + o, bdh0 + o, TG_IDESC, en);
                mma_f16_ss(tmem,       adh + o, bdl0 + o, TG_IDESC, 1u);
                mma_f16_ss(tmem,       adl + o, bdh0 + o, TG_IDESC, 1u);
                mma_f16_ss(tmem + 128, adh + o, bdh1 + o, TG_IDESC, en);
                mma_f16_ss(tmem + 128, adh + o, bdl1 + o, TG_IDESC, 1u);
                mma_f16_ss(tmem + 128, adl + o, bdh1 + o, TG_IDESC, 1u);
            }
            asm volatile(
                "tcgen05.commit.cta_group::1.mbarrier::arrive::one.shared::cluster.b64 [%0];"
                :: "r"(sb + 8 + s*8) : "memory");
        }
    }
    mbar_wait(sb + 8,  ph0);
    mbar_wait(sb + 16, ph1);
    asm volatile("tcgen05.fence::after_thread_sync;" ::: "memory");

    // epilogue: warp w -> subpartition (w&3), N-half (w>>2)
    const int sp = wid & 3;
    const int nh = wid >> 2;
    const int row = rb + sp * 32 + lid;
    float*          Cf = (float*)Cv;
    __nv_bfloat16*  Cb = (__nv_bfloat16*)Cv;
#pragma unroll
    for (int cc = 0; cc < 4; cc++) {
        uint32_t r32[32];
        uint32_t ta = tmem + ((uint32_t)sp << 21) + nh * 128 + cc * 32;
        TC_LD32(r32, ta);
        asm volatile("tcgen05.wait::ld.sync.aligned;" ::: "memory");
#pragma unroll
        for (int j = 0; j < 32; j++) {
            int gc = cb + nh * 128 + cc * 32 + j;
            if (gc < N) {
                float v = __uint_as_float(r32[j]);
                if (bias) v += bias[gc];
                if (RES)  v += res[(size_t)row * N + gc];
                if (ACT)  v = 0.5f * v * (1.0f + erff(v * 0.70710678118654752f));
                if (OUTBF) {
                    __nv_bfloat16 hi, lo; split_bf16(v, hi, lo);
                    Cb [(size_t)row * N + gc] = hi;
                    Clo[(size_t)row * N + gc] = lo;
                } else {
                    Cf[(size_t)row * N + gc] = v;
                }
            }
        }
    }
    __syncthreads();
    if (wid == 0) {
        asm volatile("tcgen05.dealloc.cta_group::1.sync.aligned.b32 %0, %1;"
                     :: "r"(tmem), "r"(256u));
    }
#else
    // ================= SIMT fallback (plain sm_103 PTX pass) =================
    extern __shared__ __align__(16) char smc[];
    float* As = (float*)smc;                    // [16][128]
    float* Bs = (float*)(smc + 16*128*4);       // [16][128] (one N-half at a time)
    const int tid = threadIdx.x;
    const int rb = blockIdx.y * MT, cb = blockIdx.x * NT;
    const int tx = tid & 15, ty = tid >> 4;
    float*          Cf = (float*)Cv;
    __nv_bfloat16*  Cb = (__nv_bfloat16*)Cv;

    for (int half = 0; half < 2; half++) {
        float acc[8][8];
#pragma unroll
        for (int i = 0; i < 8; i++)
#pragma unroll
            for (int j = 0; j < 8; j++) acc[i][j] = 0.f;

        for (int k0 = 0; k0 < K; k0 += 16) {
            for (int i = tid; i < 2048; i += 256) {
                int r = i >> 4, c = i & 15;
                size_t g = (size_t)(rb + r) * K + k0 + c;
                As[c*128 + r] = __bfloat162float(Ah[g]) + __bfloat162float(Al[g]);
            }
            for (int i = tid; i < 2048; i += 256) {
                int r = i >> 4, c = i & 15;
                size_t g = (size_t)(cb + half*128 + r) * K + k0 + c;
                Bs[c*128 + r] = __bfloat162float(Bh[g]) + __bfloat162float(Bl[g]);
            }
            __syncthreads();
#pragma unroll
            for (int kk = 0; kk < 16; kk++) {
                float ar[8], br[8];
#pragma unroll
                for (int u = 0; u < 8; u++) {
                    ar[u] = As[kk*128 + ty*8 + u];
                    br[u] = Bs[kk*128 + tx*8 + u];
                }
#pragma unroll
                for (int i = 0; i < 8; i++)
#pragma unroll
                    for (int j = 0; j < 8; j++)
                        acc[i][j] = fmaf(ar[i], br[j], acc[i][j]);
            }
            __syncthreads();
        }
#pragma unroll
        for (int i = 0; i < 8; i++) {
            int r = rb + ty*8 + i;
#pragma unroll
            for (int j = 0; j < 8; j++) {
                int gc = cb + half*128 + tx*8 + j;
                if (gc < N) {
                    float v = acc[i][j];
                    if (bias) v += bias[gc];
                    if (RES)  v += res[(size_t)r * N + gc];
                    if (ACT)  v = 0.5f * v * (1.0f + erff(v * 0.70710678118654752f));
                    if (OUTBF) {
                        __nv_bfloat16 hi, lo; split_bf16(v, hi, lo);
                        Cb [(size_t)r * N + gc] = hi;
                        Clo[(size_t)r * N + gc] = lo;
                    } else {
                        Cf[(size_t)r * N + gc] = v;
                    }
                }
            }
        }
    }
#endif
}

// ---------------- flash attention (fp32, online softmax) ----------------
#define AQ 64
#define AK 32
__global__ void __launch_bounds__(256)
attn_k(const float* __restrict__ qkv,
       __nv_bfloat16* __restrict__ yh, __nv_bfloat16* __restrict__ yl) {
    int bh = blockIdx.y;
    int b = bh / HH, h = bh % HH;
    int qs = blockIdx.x * AQ;

    __shared__ float Qs[AQ][DH + 1];
    __shared__ float Ks[AK][DH + 1];
    __shared__ float Vs[AK][DH + 1];
    __shared__ float Sm[AQ][AK + 1];
    __shared__ float rm[AQ], rl[AQ], ra[AQ];

    int tid = threadIdx.x;
    int tx = tid & 15, ty = tid >> 4;

    for (int i = tid; i < AQ * DH; i += 256) {
        int r = i >> 6, c = i & 63;
        Qs[r][c] = qkv[(size_t)(b * TT + qs + r) * QKVN + h * DH + c];
    }
    if (tid < AQ) { rm[tid] = -1e30f; rl[tid] = 0.f; }
    __syncthreads();

    float O[4][4];
#pragma unroll
    for (int i = 0; i < 4; i++)
#pragma unroll
        for (int j = 0; j < 4; j++) O[i][j] = 0.f;

    int kmaxb = max(qs + AQ - 1, KMIN);
    int ntiles = (kmaxb + AK) / AK;
    const float scale = 0.125f;

    for (int kt = 0; kt < ntiles; kt++) {
        int ks0 = kt * AK;
        for (int i = tid; i < AK * DH; i += 256) {
            int r = i >> 6, c = i & 63;
            size_t gidx = (size_t)(b * TT + ks0 + r) * QKVN + h * DH + c;
            Ks[r][c] = qkv[gidx + 1024];
            Vs[r][c] = qkv[gidx + 2048];
        }
        __syncthreads();
#pragma unroll
        for (int rr = 0; rr < 4; rr++) {
            int r = ty * 4 + rr;
            int jmax = max(qs + r, KMIN);
#pragma unroll
            for (int cc = 0; cc < 2; cc++) {
                int c = tx * 2 + cc;
                float s = 0.f;
#pragma unroll
                for (int d = 0; d < DH; d++) s = fmaf(Qs[r][d], Ks[c][d], s);
                s *= scale;
                if (ks0 + c > jmax) s = -1e30f;
                Sm[r][c] = s;
            }
        }
        __syncthreads();
        if (tid < AQ) {
            float mo = rm[tid], mx = mo;
#pragma unroll
            for (int c = 0; c < AK; c++) mx = fmaxf(mx, Sm[tid][c]);
            float al = __expf(mo - mx);
            float sum = 0.f;
#pragma unroll
            for (int c = 0; c < AK; c++) {
                float p = __expf(Sm[tid][c] - mx);
                Sm[tid][c] = p; sum += p;
            }
            rm[tid] = mx; rl[tid] = rl[tid] * al + sum; ra[tid] = al;
        }
        __syncthreads();
#pragma unroll
        for (int rr = 0; rr < 4; rr++) {
            int r = ty * 4 + rr;
            float al = ra[r];
#pragma unroll
            for (int dd = 0; dd < 4; dd++) {
                int d = tx * 4 + dd;
                float a = O[rr][dd] * al;
#pragma unroll
                for (int c = 0; c < AK; c++) a = fmaf(Sm[r][c], Vs[c][d], a);
                O[rr][dd] = a;
            }
        }
        __syncthreads();
    }
#pragma unroll
    for (int rr = 0; rr < 4; rr++) {
        int r = ty * 4 + rr;
        float inv = 1.f / rl[r];
#pragma unroll
        for (int dd = 0; dd < 4; dd++) {
            float v = O[rr][dd] * inv;
            __nv_bfloat16 hi, lo; split_bf16(v, hi, lo);
            size_t go = (size_t)(b * TT + qs + r) * DD + h * DH + tx * 4 + dd;
            yh[go] = hi;
            yl[go] = lo;
        }
    }
}

// ---------------- host orchestration ----------------
extern "C" void kernel_launch(void* const* d_in, const int* in_sizes, int n_in,
                              void* d_out, int out_size) {
    const int*   idx     = (const int*)  d_in[0];
    const float* tok_emb = (const float*)d_in[1];
    const float* ln1_w   = (const float*)d_in[2];
    const float* ln1_b   = (const float*)d_in[3];
    const float* Wq      = (const float*)d_in[4];
    const float* bq      = (const float*)d_in[5];
    const float* Wk      = (const float*)d_in[6];
    const float* bk      = (const float*)d_in[7];
    const float* Wv      = (const float*)d_in[8];
    const float* bv      = (const float*)d_in[9];
    const float* Wp      = (const float*)d_in[10];
    const float* bp      = (const float*)d_in[11];
    const float* ln2_w   = (const float*)d_in[12];
    const float* ln2_b   = (const float*)d_in[13];
    const float* W1      = (const float*)d_in[14];
    const float* b1      = (const float*)d_in[15];
    const float* W2      = (const float*)d_in[16];
    const float* b2      = (const float*)d_in[17];
    const float* lnf_w   = (const float*)d_in[18];
    const float* lnf_b   = (const float*)d_in[19];
    const float* head_w  = (const float*)d_in[20];
    float* out = (float*)d_out;

    float *x, *qkv, *bqkv;
    __nv_bfloat16 *hh, *hl, *yh, *yl, *m1h, *m1l;
    __nv_bfloat16 *wqkvh, *wqkvl, *wph, *wpl, *w1h, *w1l, *w2h, *w2l, *whh, *whl;
    cudaGetSymbolAddress((void**)&x,     g_x);
    cudaGetSymbolAddress((void**)&hh,    g_hh);
    cudaGetSymbolAddress((void**)&hl,    g_hl);
    cudaGetSymbolAddress((void**)&qkv,   g_qkv);
    cudaGetSymbolAddress((void**)&yh,    g_yh);
    cudaGetSymbolAddress((void**)&yl,    g_yl);
    cudaGetSymbolAddress((void**)&m1h,   g_m1h);
    cudaGetSymbolAddress((void**)&m1l,   g_m1l);
    cudaGetSymbolAddress((void**)&wqkvh, g_wqkvh);
    cudaGetSymbolAddress((void**)&wqkvl, g_wqkvl);
    cudaGetSymbolAddress((void**)&wph,   g_wph);
    cudaGetSymbolAddress((void**)&wpl,   g_wpl);
    cudaGetSymbolAddress((void**)&w1h,   g_w1h);
    cudaGetSymbolAddress((void**)&w1l,   g_w1l);
    cudaGetSymbolAddress((void**)&w2h,   g_w2h);
    cudaGetSymbolAddress((void**)&w2l,   g_w2l);
    cudaGetSymbolAddress((void**)&whh,   g_whh);
    cudaGetSymbolAddress((void**)&whl,   g_whl);
    cudaGetSymbolAddress((void**)&bqkv,  g_bqkv);

    cudaFuncSetAttribute(tgemm_k<0,0,0>, cudaFuncAttributeMaxDynamicSharedMemorySize, SMEMB);
    cudaFuncSetAttribute(tgemm_k<0,0,1>, cudaFuncAttributeMaxDynamicSharedMemorySize, SMEMB);
    cudaFuncSetAttribute(tgemm_k<1,1,0>, cudaFuncAttributeMaxDynamicSharedMemorySize, SMEMB);

    dim3 tb(32, 8);
    for (int l = 0; l < LL; l++) {
        const float* wq_l = Wq + (size_t)l*DD*DD;
        const float* wk_l = Wk + (size_t)l*DD*DD;
        const float* wv_l = Wv + (size_t)l*DD*DD;
        const float* wp_l = Wp + (size_t)l*DD*DD;
        const float* w1_l = W1 + (size_t)l*DD*FF;
        const float* w2_l = W2 + (size_t)l*FF*DD;
        size_t oq = (size_t)l*QKVN*DD;
        convT_k<<<dim3(DD/32, DD/32), tb>>>(wq_l, wqkvh + oq,                   wqkvl + oq,                   DD, DD);
        convT_k<<<dim3(DD/32, DD/32), tb>>>(wk_l, wqkvh + oq + (size_t)1024*DD, wqkvl + oq + (size_t)1024*DD, DD, DD);
        convT_k<<<dim3(DD/32, DD/32), tb>>>(wv_l, wqkvh + oq + (size_t)2048*DD, wqkvl + oq + (size_t)2048*DD, DD, DD);
        convT_k<<<dim3(DD/32, DD/32), tb>>>(wp_l, wph + (size_t)l*DD*DD, wpl + (size_t)l*DD*DD, DD, DD);
        convT_k<<<dim3(FF/32, DD/32), tb>>>(w1_l, w1h + (size_t)l*FF*DD, w1l + (size_t)l*FF*DD, DD, FF);
        convT_k<<<dim3(DD/32, FF/32), tb>>>(w2_l, w2h + (size_t)l*DD*FF, w2l + (size_t)l*DD*FF, FF, DD);
    }
    convT_k<<<dim3(VPAD/32, DD/32), tb>>>(head_w, whh, whl, DD, VV);
    cat_bias_k<<<LL, 1024>>>(bq, bk, bv, bqkv);

    embed_k<<<MM_, 256>>>(idx, tok_emb, x);

    dim3 gQKV (QKVN/NT, MM_/MT);   // 12 x 32
    dim3 gPROJ(DD/NT,   MM_/MT);   // 4 x 32
    dim3 gMLP1(FF/NT,   MM_/MT);   // 16 x 32
    dim3 gHEAD(VPAD/NT, MM_/MT);   // 197 x 32
    dim3 gAtt (TT/AQ, BB*HH);

    for (int l = 0; l < LL; l++) {
        const size_t oD = (size_t)l * DD;
        const size_t oq = (size_t)l*QKVN*DD;

        ln_k<<<MM_, 256>>>(x, ln1_w + oD, ln1_b + oD, hh, hl);
        tgemm_k<0,0,0><<<gQKV, 256, SMEMB>>>(hh, hl, wqkvh + oq, wqkvl + oq,
                                             bqkv + l*QKVN, nullptr, qkv, nullptr,
                                             MM_, QKVN, DD);
        attn_k<<<gAtt, 256>>>(qkv, yh, yl);
        tgemm_k<0,0,1><<<gPROJ, 256, SMEMB>>>(yh, yl,
                                              wph + (size_t)l*DD*DD, wpl + (size_t)l*DD*DD,
                                              bp + oD, x, x, nullptr, MM_, DD, DD);

        ln_k<<<MM_, 256>>>(x, ln2_w + oD, ln2_b + oD, hh, hl);
        tgemm_k<1,1,0><<<gMLP1, 256, SMEMB>>>(hh, hl,
                                              w1h + (size_t)l*FF*DD, w1l + (size_t)l*FF*DD,
                                              b1 + (size_t)l*FF, nullptr, m1h, m1l,
                                              MM_, FF, DD);
        tgemm_k<0,0,1><<<gPROJ, 256, SMEMB>>>(m1h, m1l,
                                              w2h + (size_t)l*DD*FF, w2l + (size_t)l*DD*FF,
                                              b2 + oD, x, x, nullptr, MM_, DD, FF);
    }

    ln_k<<<MM_, 256>>>(x, lnf_w, lnf_b, hh, hl);
    tgemm_k<0,0,0><<<gHEAD, 256, SMEMB>>>(hh, hl, whh, whl, nullptr, nullptr,
                                          out, nullptr, MM_, VV, DD);
}